// round 11
// baseline (speedup 1.0000x reference)
#include <cuda_runtime.h>
#include <cstdint>

// Published selection results. g_idx sentinel -1 gates the first call only;
// replays see identical recomputed values (inputs are fixed), so any
// read/write overlap is of identical words -> deterministic.
__device__ volatile int g_idx[64] = {
    -1,-1,-1,-1,-1,-1,-1,-1, -1,-1,-1,-1,-1,-1,-1,-1,
    -1,-1,-1,-1,-1,-1,-1,-1, -1,-1,-1,-1,-1,-1,-1,-1,
    -1,-1,-1,-1,-1,-1,-1,-1, -1,-1,-1,-1,-1,-1,-1,-1,
    -1,-1,-1,-1,-1,-1,-1,-1, -1,-1,-1,-1,-1,-1,-1,-1};
__device__ float g_w[64];

// ---------------------------------------------------------------------------
// One warp computes the (index, weight) of Gumbel-top-k rank `rank`.
// 64 logits; each lane owns entries {lane, lane+32}.
// Publishes g_w[rank] then (release) g_idx[rank].
// ---------------------------------------------------------------------------
__device__ __forceinline__ void rank_select(const float* __restrict__ logit,
                                            const float* __restrict__ bg,
                                            const float* __restrict__ gumbel,
                                            int rank) {
    const int lane = threadIdx.x & 31;

    float p0 = logit[lane]      + logf(fmaxf(1.0f - bg[lane],      1e-8f))
             + gumbel[lane];
    float p1 = logit[lane + 32] + logf(fmaxf(1.0f - bg[lane + 32], 1e-8f))
             + gumbel[lane + 32];
    float m0 = 0.0f, m1 = 0.0f;

    for (int it = 0; it <= rank; ++it) {
        float v0 = p0 + m0;
        float v1 = p1 + m1;
        // local argmax, tie -> lower index
        float best = v0;
        int bi = lane;
        if (v1 > best) { best = v1; bi = lane + 32; }
        // warp argmax reduction, tie -> lower index
        #pragma unroll
        for (int off = 16; off > 0; off >>= 1) {
            float ob = __shfl_xor_sync(0xffffffffu, best, off);
            int   oi = __shfl_xor_sync(0xffffffffu, bi,   off);
            if (ob > best || (ob == best && oi < bi)) { best = ob; bi = oi; }
        }
        if (it == rank) {
            // softmax value at argmax: 1/sum_j exp((v_j - best)/tau), tau=0.01
            float s = expf((v0 - best) * 100.0f) + expf((v1 - best) * 100.0f);
            #pragma unroll
            for (int off = 16; off > 0; off >>= 1)
                s += __shfl_xor_sync(0xffffffffu, s, off);
            if (lane == 0) {
                g_w[rank] = 1.0f / s;
                __threadfence();              // release: w before idx
                g_idx[rank] = bi;
            }
        } else {
            if (bi == lane)      m0 = -1e9f;
            if (bi == lane + 32) m1 = -1e9f;
        }
    }
}

// ---------------------------------------------------------------------------
// Single fused kernel.
//   blocks [0, kk*1024)              : image gather (scaled by w_k)
//   blocks [kk*1024, kk*1024+kk*256) : label gather (unscaled)
// Block 0 additionally computes the selection (one warp per rank) and the
// masked_logit output; every block acquires (idx_k, w_k) via a volatile poll.
// One float4 per thread; patch rows are 16 contiguous float4 -> coalesced.
// ---------------------------------------------------------------------------
__global__ void __launch_bounds__(256)
gather_kernel(const float* __restrict__ img,
              const float* __restrict__ lab,
              const float* __restrict__ logit,
              const float* __restrict__ bg,
              const float* __restrict__ gumbel,
              float* __restrict__ out_img,
              float* __restrict__ out_lab,
              float* __restrict__ out_logit,
              int img_blocks,                 // kk * 1024
              int kk) {
    if (blockIdx.x == 0) {
        // masked_logit output (64 values), threads 0..63
        if (threadIdx.x < 64)
            out_logit[threadIdx.x] =
                logit[threadIdx.x] +
                logf(fmaxf(1.0f - bg[threadIdx.x], 1e-8f));
        // one warp per rank (8 warps cover kk<=8; loop for larger kk)
        const int wid = threadIdx.x >> 5;
        for (int rank = wid; rank < kk; rank += 8)
            rank_select(logit, bg, gumbel, rank);
    }

    const bool is_img = (int)blockIdx.x < img_blocks;
    const int  lb     = is_img ? (int)blockIdx.x : (int)blockIdx.x - img_blocks;
    const int  my_k   = is_img ? (lb >> 10) : (lb >> 8);

    // acquire (idx, w) for my rank
    int n;
    do { n = g_idx[my_k]; } while (n < 0);
    __threadfence();
    const float w = __ldcg((const float*)&g_w[my_k]);

    const int hn = n >> 4, wn = (n >> 2) & 3, dn = n & 3;

    if (is_img) {
        const unsigned i = (unsigned)lb * 256u + threadIdx.x;  // < 2^21
        int r   = i & ((4 << 16) - 1);                 // offset within this k
        int c   = r >> 16;
        int off = r & 65535;
        int dp4 = off & 15, wp = (off >> 4) & 63, hp = off >> 10;
        long src = (long)c * 16777216
                 + (long)(hn * 64 + hp) * 65536
                 + (long)(wn * 64 + wp) * 256
                 + (long)(dn * 64 + dp4 * 4);
        float4 v = *(const float4*)(img + src);
        v.x *= w; v.y *= w; v.z *= w; v.w *= w;
        ((float4*)out_img)[i] = v;
    } else {
        const unsigned j = (unsigned)lb * 256u + threadIdx.x;  // < 2^19
        int off = j & 65535;
        int dp4 = off & 15, wp = (off >> 4) & 63, hp = off >> 10;
        long src = (long)(hn * 64 + hp) * 65536
                 + (long)(wn * 64 + wp) * 256
                 + (long)(dn * 64 + dp4 * 4);
        ((float4*)out_lab)[j] = *(const float4*)(lab + src);
    }
}

extern "C" void kernel_launch(void* const* d_in, const int* in_sizes, int n_in,
                              void* d_out, int out_size) {
    const float* image  = (const float*)d_in[0];   // [1,4,256,256,256]
    const float* label  = (const float*)d_in[1];   // [1,1,256,256,256]
    const float* logit  = (const float*)d_in[2];   // [1,1,4,4,4]
    const float* bg     = (const float*)d_in[3];   // [1,1,4,4,4]
    const float* gumbel = (const float*)d_in[4];   // [1,64]

    // k derived from the output size: out = k*(4+1)*64^3 + 64 floats
    int kk = (int)(((long)out_size - 64) / (5L * 262144));
    if (kk < 1 || kk > 64) kk = 8;

    float* out       = (float*)d_out;
    float* out_lab   = out + (long)kk * 4 * 262144;        // after img block
    float* out_logit = out_lab + (long)kk * 262144;        // after lab block

    const int img_blocks = kk * 1024;
    const int lab_blocks = kk * 256;
    gather_kernel<<<img_blocks + lab_blocks, 256>>>(
        image, label, logit, bg, gumbel, out, out_lab, out_logit,
        img_blocks, kk);
}

// round 12
// speedup vs baseline: 2.4270x; 2.4270x over previous
#include <cuda_runtime.h>
#include <cstdint>

// Selection results, produced by select_kernel, consumed by gather_kernel.
// Kernel boundary (graph edge) provides all ordering.
__device__ int   g_idx[64];
__device__ float g_w[64];

// Map float to an orderable uint32 (monotone: a<b  <=>  ord(a)<ord(b)).
__device__ __forceinline__ unsigned ford(float f) {
    unsigned u = __float_as_uint(f);
    return (u & 0x80000000u) ? ~u : (u | 0x80000000u);
}

// ---------------------------------------------------------------------------
// Select kernel: 1 block, 256 threads = 8 warps; warp r computes Gumbel
// top-k rank r (stride 8 for kk > 8). Each lane owns entries {lane, lane+32}
// of the 64 perturbed logits. Argmax per iteration via __reduce_max_sync on
// orderable bits + ballot (exact, lowest-index tie-break). Softmax weight
// computed only at the warp's own rank. Threads 0..63 also write masked_logit.
// ---------------------------------------------------------------------------
__global__ void __launch_bounds__(256)
select_kernel(const float* __restrict__ logit,
              const float* __restrict__ bg,
              const float* __restrict__ gumbel,
              float* __restrict__ out_logit,
              int kk) {
    const int lane = threadIdx.x & 31;
    const int wid  = threadIdx.x >> 5;

    float ml0 = logit[lane]      + logf(fmaxf(1.0f - bg[lane],      1e-8f));
    float ml1 = logit[lane + 32] + logf(fmaxf(1.0f - bg[lane + 32], 1e-8f));
    if (wid == 0) {                       // masked_logit output (64 values)
        out_logit[lane]      = ml0;
        out_logit[lane + 32] = ml1;
    }

    const float q0 = ml0 + gumbel[lane];
    const float q1 = ml1 + gumbel[lane + 32];

    for (int rank = wid; rank < kk; rank += 8) {
        float p0 = q0, p1 = q1;           // fresh copy; mask applied in place
        for (int it = 0; it <= rank; ++it) {
            // warp max of 64 values via redux on orderable bits
            unsigned o = max(ford(p0), ford(p1));
            unsigned mo = __reduce_max_sync(0xffffffffu, o);
            // index of max, tie -> lowest index (slot0 indices < slot1)
            unsigned b0 = __ballot_sync(0xffffffffu, ford(p0) == mo);
            unsigned b1 = __ballot_sync(0xffffffffu, ford(p1) == mo);
            int bi = b0 ? (__ffs(b0) - 1) : (32 + __ffs(b1) - 1);

            if (it == rank) {
                // best as float (recover from lane owning it)
                float best = __shfl_sync(0xffffffffu, bi < 32 ? p0 : p1,
                                         bi & 31);
                // softmax value at argmax: 1/sum exp((v-best)/tau), tau=0.01
                float s = expf((p0 - best) * 100.0f)
                        + expf((p1 - best) * 100.0f);
                #pragma unroll
                for (int off = 16; off > 0; off >>= 1)
                    s += __shfl_xor_sync(0xffffffffu, s, off);
                if (lane == 0) { g_idx[rank] = bi; g_w[rank] = 1.0f / s; }
            } else {
                if (bi == lane)      p0 = q0 - 1e9f;
                if (bi == lane + 32) p1 = q1 - 1e9f;
            }
        }
    }
}

// ---------------------------------------------------------------------------
// Fused gather: one grid covers image (scaled by w_k) and label (unscaled).
//   blocks [0, kk*1024)              : image — 1024 blocks per k
//   blocks [kk*1024, kk*1024+kk*256) : label — 256 blocks per k
// One float4 per thread; patch row = 16 contiguous float4 -> coalesced.
// Streaming (__stcg) stores keep the read patches resident in L2 across
// graph replays.
// ---------------------------------------------------------------------------
__global__ void __launch_bounds__(256)
gather_kernel(const float* __restrict__ img,
              const float* __restrict__ lab,
              float* __restrict__ out_img,
              float* __restrict__ out_lab,
              int img_blocks) {               // kk * 1024
    const bool is_img = (int)blockIdx.x < img_blocks;
    const int  lb     = is_img ? (int)blockIdx.x : (int)blockIdx.x - img_blocks;
    const int  my_k   = is_img ? (lb >> 10) : (lb >> 8);

    const int   n  = g_idx[my_k];
    const float w  = g_w[my_k];
    const int hn = n >> 4, wn = (n >> 2) & 3, dn = n & 3;

    if (is_img) {
        const unsigned i = (unsigned)lb * 256u + threadIdx.x;  // < 2^21
        int r   = i & ((4 << 16) - 1);                 // offset within this k
        int c   = r >> 16;
        int off = r & 65535;
        int dp4 = off & 15, wp = (off >> 4) & 63, hp = off >> 10;
        long src = (long)c * 16777216
                 + (long)(hn * 64 + hp) * 65536
                 + (long)(wn * 64 + wp) * 256
                 + (long)(dn * 64 + dp4 * 4);
        float4 v = *(const float4*)(img + src);
        v.x *= w; v.y *= w; v.z *= w; v.w *= w;
        __stcg((float4*)out_img + i, v);
    } else {
        const unsigned j = (unsigned)lb * 256u + threadIdx.x;  // < 2^19
        int off = j & 65535;
        int dp4 = off & 15, wp = (off >> 4) & 63, hp = off >> 10;
        long src = (long)(hn * 64 + hp) * 65536
                 + (long)(wn * 64 + wp) * 256
                 + (long)(dn * 64 + dp4 * 4);
        float4 v = *(const float4*)(lab + src);
        __stcg((float4*)out_lab + j, v);
    }
}

extern "C" void kernel_launch(void* const* d_in, const int* in_sizes, int n_in,
                              void* d_out, int out_size) {
    const float* image  = (const float*)d_in[0];   // [1,4,256,256,256]
    const float* label  = (const float*)d_in[1];   // [1,1,256,256,256]
    const float* logit  = (const float*)d_in[2];   // [1,1,4,4,4]
    const float* bg     = (const float*)d_in[3];   // [1,1,4,4,4]
    const float* gumbel = (const float*)d_in[4];   // [1,64]

    // k derived from the output size: out = k*(4+1)*64^3 + 64 floats
    int kk = (int)(((long)out_size - 64) / (5L * 262144));
    if (kk < 1 || kk > 64) kk = 8;

    float* out       = (float*)d_out;
    float* out_lab   = out + (long)kk * 4 * 262144;        // after img block
    float* out_logit = out_lab + (long)kk * 262144;        // after lab block

    select_kernel<<<1, 256>>>(logit, bg, gumbel, out_logit, kk);

    const int img_blocks = kk * 1024;
    const int lab_blocks = kk * 256;
    gather_kernel<<<img_blocks + lab_blocks, 256>>>(
        image, label, out, out_lab, img_blocks);
}

// round 15
// speedup vs baseline: 2.7284x; 1.1242x over previous
#include <cuda_runtime.h>
#include <cstdint>

// Selection results, produced by select_kernel, consumed by gather_kernel.
// Kernel boundary (graph edge) provides all ordering.
__device__ int   g_idx[64];
__device__ float g_w[64];

// Map float to an orderable uint32 (monotone: a<b  <=>  ord(a)<ord(b)).
__device__ __forceinline__ unsigned ford(float f) {
    unsigned u = __float_as_uint(f);
    return (u & 0x80000000u) ? ~u : (u | 0x80000000u);
}

// ---------------------------------------------------------------------------
// Select kernel: 1 block, 256 threads = 8 warps; warp r computes Gumbel
// top-k rank r (stride 8 for kk > 8). Each lane owns entries {lane, lane+32}
// of the 64 perturbed logits. Argmax per iteration via __reduce_max_sync on
// orderable bits + ballot (exact, lowest-index tie-break). Softmax weight
// computed only at the warp's own rank. Warp 0 also writes masked_logit.
// ---------------------------------------------------------------------------
__global__ void __launch_bounds__(256)
select_kernel(const float* __restrict__ logit,
              const float* __restrict__ bg,
              const float* __restrict__ gumbel,
              float* __restrict__ out_logit,
              int kk) {
    const int lane = threadIdx.x & 31;
    const int wid  = threadIdx.x >> 5;

    float ml0 = logit[lane]      + logf(fmaxf(1.0f - bg[lane],      1e-8f));
    float ml1 = logit[lane + 32] + logf(fmaxf(1.0f - bg[lane + 32], 1e-8f));
    if (wid == 0) {                       // masked_logit output (64 values)
        out_logit[lane]      = ml0;
        out_logit[lane + 32] = ml1;
    }

    const float q0 = ml0 + gumbel[lane];
    const float q1 = ml1 + gumbel[lane + 32];

    for (int rank = wid; rank < kk; rank += 8) {
        float p0 = q0, p1 = q1;           // fresh copy; mask applied in place
        for (int it = 0; it <= rank; ++it) {
            // warp max of 64 values via redux on orderable bits
            unsigned o = max(ford(p0), ford(p1));
            unsigned mo = __reduce_max_sync(0xffffffffu, o);
            // index of max, tie -> lowest index (slot0 indices < slot1)
            unsigned b0 = __ballot_sync(0xffffffffu, ford(p0) == mo);
            unsigned b1 = __ballot_sync(0xffffffffu, ford(p1) == mo);
            int bi = b0 ? (__ffs(b0) - 1) : (32 + __ffs(b1) - 1);

            if (it == rank) {
                // best as float (recover from lane owning it)
                float best = __shfl_sync(0xffffffffu, bi < 32 ? p0 : p1,
                                         bi & 31);
                // softmax value at argmax: 1/sum exp((v-best)/tau), tau=0.01
                float s = expf((p0 - best) * 100.0f)
                        + expf((p1 - best) * 100.0f);
                #pragma unroll
                for (int off = 16; off > 0; off >>= 1)
                    s += __shfl_xor_sync(0xffffffffu, s, off);
                if (lane == 0) { g_idx[rank] = bi; g_w[rank] = 1.0f / s; }
            } else {
                if (bi == lane)      p0 = q0 - 1e9f;
                if (bi == lane + 32) p1 = q1 - 1e9f;
            }
        }
    }
}

// ---------------------------------------------------------------------------
// Fused gather with 8x ILP per thread.
//   blocks [0, kk*128)             : image — 128 blocks per k (4c x 32)
//   blocks [kk*128, kk*128+kk*32)  : label — 32 blocks per k
// Each thread owns q in [0,8192) of one (k,c) patch volume and processes the
// 8 float4 at off = q + j*8192 (j=0..7). That stride leaves dp4/wp fixed and
// advances hp by 8 -> constant source stride of 8*65536 floats. 8 independent
// LDG.128 per thread (MLP=8), then scale+store. Lanes own consecutive q ->
// fully coalesced.
// ---------------------------------------------------------------------------
__global__ void __launch_bounds__(256)
gather_kernel(const float* __restrict__ img,
              const float* __restrict__ lab,
              float* __restrict__ out_img,
              float* __restrict__ out_lab,
              int img_blocks) {               // kk * 128
    const bool is_img = (int)blockIdx.x < img_blocks;
    const int  lb     = is_img ? (int)blockIdx.x : (int)blockIdx.x - img_blocks;

    int my_k, c;
    if (is_img) { my_k = lb >> 7; c = (lb >> 5) & 3; }
    else        { my_k = lb >> 5; c = 0;             }
    const int qbase = (lb & 31) << 8;

    const int   n = g_idx[my_k];
    const float w = is_img ? g_w[my_k] : 1.0f;
    const int hn = n >> 4, wn = (n >> 2) & 3, dn = n & 3;

    const int q   = qbase + (int)threadIdx.x;    // [0, 8192)
    const int hp  = q >> 10;                     // [0, 8)
    const int wp  = (q >> 4) & 63;
    const int dp4 = q & 15;

    const float* src = (is_img ? img + (long)c * 16777216 : lab)
                     + (long)(hn * 64 + hp) * 65536
                     + (long)(wn * 64 + wp) * 256
                     + (long)(dn * 64 + dp4 * 4);

    float4 v[8];
    #pragma unroll
    for (int j = 0; j < 8; ++j)
        v[j] = *(const float4*)(src + (long)j * 524288);  // +8 hp planes

    float4* dst = (is_img ? (float4*)out_img + ((long)(my_k * 4 + c) << 16)
                          : (float4*)out_lab + ((long)my_k << 16)) + q;
    #pragma unroll
    for (int j = 0; j < 8; ++j) {
        float4 t = v[j];
        t.x *= w; t.y *= w; t.z *= w; t.w *= w;
        dst[(long)j * 8192] = t;
    }
}

extern "C" void kernel_launch(void* const* d_in, const int* in_sizes, int n_in,
                              void* d_out, int out_size) {
    const float* image  = (const float*)d_in[0];   // [1,4,256,256,256]
    const float* label  = (const float*)d_in[1];   // [1,1,256,256,256]
    const float* logit  = (const float*)d_in[2];   // [1,1,4,4,4]
    const float* bg     = (const float*)d_in[3];   // [1,1,4,4,4]
    const float* gumbel = (const float*)d_in[4];   // [1,64]

    // k derived from the output size: out = k*(4+1)*64^3 + 64 floats
    int kk = (int)(((long)out_size - 64) / (5L * 262144));
    if (kk < 1 || kk > 64) kk = 8;

    float* out       = (float*)d_out;
    float* out_lab   = out + (long)kk * 4 * 262144;        // after img block
    float* out_logit = out_lab + (long)kk * 262144;        // after lab block

    select_kernel<<<1, 256>>>(logit, bg, gumbel, out_logit, kk);

    const int img_blocks = kk * 128;
    const int lab_blocks = kk * 32;
    gather_kernel<<<img_blocks + lab_blocks, 256>>>(
        image, label, out, out_lab, img_blocks);
}

// round 16
// speedup vs baseline: 2.7458x; 1.0064x over previous
#include <cuda_runtime.h>
#include <cstdint>

// Selection results, produced by select_kernel, consumed by gather_kernel.
// Kernel boundary (graph edge) provides all ordering.
__device__ int   g_idx[64];
__device__ float g_w[64];

// Map float to an orderable uint32 (monotone: a<b  <=>  ord(a)<ord(b)).
__device__ __forceinline__ unsigned ford(float f) {
    unsigned u = __float_as_uint(f);
    return (u & 0x80000000u) ? ~u : (u | 0x80000000u);
}

// ---------------------------------------------------------------------------
// Select kernel: 1 block, 256 threads = 8 warps; warp r computes Gumbel
// top-k rank r (stride 8 for kk > 8). Each lane owns entries {lane, lane+32}
// of the 64 perturbed logits. Argmax per iteration via __reduce_max_sync on
// orderable bits + ballot (exact, lowest-index tie-break). Softmax weight
// computed only at the warp's own rank. Warp 0 also writes masked_logit.
// ---------------------------------------------------------------------------
__global__ void __launch_bounds__(256)
select_kernel(const float* __restrict__ logit,
              const float* __restrict__ bg,
              const float* __restrict__ gumbel,
              float* __restrict__ out_logit,
              int kk) {
    const int lane = threadIdx.x & 31;
    const int wid  = threadIdx.x >> 5;

    float ml0 = logit[lane]      + logf(fmaxf(1.0f - bg[lane],      1e-8f));
    float ml1 = logit[lane + 32] + logf(fmaxf(1.0f - bg[lane + 32], 1e-8f));
    if (wid == 0) {                       // masked_logit output (64 values)
        out_logit[lane]      = ml0;
        out_logit[lane + 32] = ml1;
    }

    const float q0 = ml0 + gumbel[lane];
    const float q1 = ml1 + gumbel[lane + 32];

    for (int rank = wid; rank < kk; rank += 8) {
        float p0 = q0, p1 = q1;           // fresh copy; mask applied in place
        for (int it = 0; it <= rank; ++it) {
            // warp max of 64 values via redux on orderable bits
            unsigned o = max(ford(p0), ford(p1));
            unsigned mo = __reduce_max_sync(0xffffffffu, o);
            // index of max, tie -> lowest index (slot0 indices < slot1)
            unsigned b0 = __ballot_sync(0xffffffffu, ford(p0) == mo);
            unsigned b1 = __ballot_sync(0xffffffffu, ford(p1) == mo);
            int bi = b0 ? (__ffs(b0) - 1) : (32 + __ffs(b1) - 1);

            if (it == rank) {
                // best as float (recover from lane owning it)
                float best = __shfl_sync(0xffffffffu, bi < 32 ? p0 : p1,
                                         bi & 31);
                // softmax value at argmax: 1/sum exp((v-best)/tau), tau=0.01
                float s = expf((p0 - best) * 100.0f)
                        + expf((p1 - best) * 100.0f);
                #pragma unroll
                for (int off = 16; off > 0; off >>= 1)
                    s += __shfl_xor_sync(0xffffffffu, s, off);
                if (lane == 0) { g_idx[rank] = bi; g_w[rank] = 1.0f / s; }
            } else {
                if (bi == lane)      p0 = q0 - 1e9f;
                if (bi == lane + 32) p1 = q1 - 1e9f;
            }
        }
    }
}

// ---------------------------------------------------------------------------
// Fused gather, 8 float4 per thread in TWO batches of 4 (MLP_p1 = 4).
//   blocks [0, kk*128)             : image — 128 blocks per k (4c x 32)
//   blocks [kk*128, kk*128+kk*32)  : label — 32 blocks per k
// Each thread owns q in [0,8192) of one (k,c) patch volume and handles the
// 8 float4 at off = q + j*8192. Constant source stride (8 hp planes); lanes
// own consecutive q -> fully coalesced. Batching 4 loads + 4 stores twice
// keeps the front-batched LDG count at 4, cutting cross-CTA L1tex-queue
// spread (B300 spr_max ~2.0 @MLP8 -> ~1.3 @MLP4) while retaining the 8x
// per-thread amortization.
// ---------------------------------------------------------------------------
__global__ void __launch_bounds__(256)
gather_kernel(const float* __restrict__ img,
              const float* __restrict__ lab,
              float* __restrict__ out_img,
              float* __restrict__ out_lab,
              int img_blocks) {               // kk * 128
    const bool is_img = (int)blockIdx.x < img_blocks;
    const int  lb     = is_img ? (int)blockIdx.x : (int)blockIdx.x - img_blocks;

    int my_k, c;
    if (is_img) { my_k = lb >> 7; c = (lb >> 5) & 3; }
    else        { my_k = lb >> 5; c = 0;             }
    const int qbase = (lb & 31) << 8;

    const int   n = g_idx[my_k];
    const float w = is_img ? g_w[my_k] : 1.0f;
    const int hn = n >> 4, wn = (n >> 2) & 3, dn = n & 3;

    const int q   = qbase + (int)threadIdx.x;    // [0, 8192)
    const int hp  = q >> 10;                     // [0, 8)
    const int wp  = (q >> 4) & 63;
    const int dp4 = q & 15;

    const float* src = (is_img ? img + (long)c * 16777216 : lab)
                     + (long)(hn * 64 + hp) * 65536
                     + (long)(wn * 64 + wp) * 256
                     + (long)(dn * 64 + dp4 * 4);

    float4* dst = (is_img ? (float4*)out_img + ((long)(my_k * 4 + c) << 16)
                          : (float4*)out_lab + ((long)my_k << 16)) + q;

    // batch 0: j = 0..3
    float4 v[4];
    #pragma unroll
    for (int j = 0; j < 4; ++j)
        v[j] = *(const float4*)(src + (long)j * 524288);  // +8 hp planes
    #pragma unroll
    for (int j = 0; j < 4; ++j) {
        float4 t = v[j];
        t.x *= w; t.y *= w; t.z *= w; t.w *= w;
        dst[(long)j * 8192] = t;
    }

    // batch 1: j = 4..7
    #pragma unroll
    for (int j = 0; j < 4; ++j)
        v[j] = *(const float4*)(src + (long)(j + 4) * 524288);
    #pragma unroll
    for (int j = 0; j < 4; ++j) {
        float4 t = v[j];
        t.x *= w; t.y *= w; t.z *= w; t.w *= w;
        dst[(long)(j + 4) * 8192] = t;
    }
}

extern "C" void kernel_launch(void* const* d_in, const int* in_sizes, int n_in,
                              void* d_out, int out_size) {
    const float* image  = (const float*)d_in[0];   // [1,4,256,256,256]
    const float* label  = (const float*)d_in[1];   // [1,1,256,256,256]
    const float* logit  = (const float*)d_in[2];   // [1,1,4,4,4]
    const float* bg     = (const float*)d_in[3];   // [1,1,4,4,4]
    const float* gumbel = (const float*)d_in[4];   // [1,64]

    // k derived from the output size: out = k*(4+1)*64^3 + 64 floats
    int kk = (int)(((long)out_size - 64) / (5L * 262144));
    if (kk < 1 || kk > 64) kk = 8;

    float* out       = (float*)d_out;
    float* out_lab   = out + (long)kk * 4 * 262144;        // after img block
    float* out_logit = out_lab + (long)kk * 262144;        // after lab block

    select_kernel<<<1, 256>>>(logit, bg, gumbel, out_logit, kk);

    const int img_blocks = kk * 128;
    const int lab_blocks = kk * 32;
    gather_kernel<<<img_blocks + lab_blocks, 256>>>(
        image, label, out, out_lab, img_blocks);
}